// round 2
// baseline (speedup 1.0000x reference)
#include <cuda_runtime.h>

// ---------------------------------------------------------------------------
// BahdanauAttention (Keras AdditiveAttention) on GB300
//   q = dec_query @ W1            [B,Tq,U]
//   k = enc_values @ W2           [B,Tv,U]
//   scores[b,q,v] = sum_u scale[u] * tanh(q[b,q,u] + k[b,v,u])
//   weights = softmax_v(scores)
//   context = weights @ k
//   output = concat(context.flat, weights.flat)
//
// Shapes fixed by the dataset: B=4, Tq=256, Tv=2048, Dq=Dv=512, U=128.
//
// tanh(x) = 1 - 2/(exp(2x)+1).  Projections pre-scaled by 2*log2(e) so the
// inner loop is: e = ex2(qc+kc); r = 1/(e+1); acc += (-2*scale)*r.
// The reciprocal is computed on the MUFU pipe (rcp.approx) for half the
// u-lanes and on the FMA/ALU pipes (magic-constant + 2 Newton iterations,
// rel err ~6e-6) for the other half, balancing MUFU (rt 8) against fma (rt 2):
// per element-pair MUFU = 24 cyc, fma-pipe = 20 cyc  (was MUFU 32 / fma 12).
// ---------------------------------------------------------------------------

#define BB 4
#define TQ 256
#define TV 2048
#define DK 512
#define UU 128
#define QB 8          // q-rows per attention CTA

#define C2LOG2E 2.8853900817779268f   // 2*log2(e)
#define LOG2E   1.4426950408889634f

// Scratch (device globals: no allocation allowed in kernel_launch)
__device__ float g_qc[BB * TQ * UU];   // 2*log2e * (dec_query @ W1)
__device__ float g_k [BB * TV * UU];   // enc_values @ W2 (raw, for context)
__device__ float g_kc[BB * TV * UU];   // 2*log2e * k

__device__ __forceinline__ float fex2(float x) {
    float y; asm("ex2.approx.ftz.f32 %0, %1;" : "=f"(y) : "f"(x)); return y;
}
__device__ __forceinline__ float frcp(float x) {
    float y; asm("rcp.approx.ftz.f32 %0, %1;" : "=f"(y) : "f"(x)); return y;
}
// FMA/ALU-pipe reciprocal: magic-constant seed (~5% err) + 2 Newton steps
// -> rel err ~6e-6.  Valid for normal positive y; here y = exp2(x)+1 >= 1.
__device__ __forceinline__ float frcp_fast(float y) {
    float r = __int_as_float(0x7EF311C3 - __float_as_int(y));
    r = r * fmaf(-y, r, 2.0f);
    r = r * fmaf(-y, r, 2.0f);
    return r;
}

// ---------------------------------------------------------------------------
// Projection GEMM: out[m, u] = sum_d X[m, d] * W[d, u],  K=512, N=128.
// 16 rows per CTA, 128 threads (thread = one output column u).
// X tile staged transposed in smem so the inner loop reads rows via LDS.128.
// KMODE=false -> writes g_qc (scaled);  KMODE=true -> writes g_k and g_kc.
// ---------------------------------------------------------------------------
template <bool KMODE>
__global__ void __launch_bounds__(128) proj_kernel(const float* __restrict__ X,
                                                   const float* __restrict__ W) {
    __shared__ __align__(16) float sXT[DK][20];  // [d][row], stride 20 floats (80B)
    const int tid = threadIdx.x;
    const int m0  = blockIdx.x * 16;

    const float4* X4 = reinterpret_cast<const float4*>(X) + (size_t)m0 * (DK / 4);
    for (int i = tid; i < 16 * (DK / 4); i += 128) {
        int row = i >> 7;        // / (DK/4)
        int d4  = i & 127;
        float4 v = X4[row * (DK / 4) + d4];
        sXT[d4 * 4 + 0][row] = v.x;
        sXT[d4 * 4 + 1][row] = v.y;
        sXT[d4 * 4 + 2][row] = v.z;
        sXT[d4 * 4 + 3][row] = v.w;
    }
    __syncthreads();

    const int u = tid;
    float acc[16];
#pragma unroll
    for (int r = 0; r < 16; r++) acc[r] = 0.f;

#pragma unroll 4
    for (int d = 0; d < DK; d++) {
        float w = __ldg(&W[d * UU + u]);
        const float4* s = reinterpret_cast<const float4*>(&sXT[d][0]);
        float4 a = s[0], b4 = s[1], c4 = s[2], e4 = s[3];
        acc[0]  = fmaf(a.x,  w, acc[0]);  acc[1]  = fmaf(a.y,  w, acc[1]);
        acc[2]  = fmaf(a.z,  w, acc[2]);  acc[3]  = fmaf(a.w,  w, acc[3]);
        acc[4]  = fmaf(b4.x, w, acc[4]);  acc[5]  = fmaf(b4.y, w, acc[5]);
        acc[6]  = fmaf(b4.z, w, acc[6]);  acc[7]  = fmaf(b4.w, w, acc[7]);
        acc[8]  = fmaf(c4.x, w, acc[8]);  acc[9]  = fmaf(c4.y, w, acc[9]);
        acc[10] = fmaf(c4.z, w, acc[10]); acc[11] = fmaf(c4.w, w, acc[11]);
        acc[12] = fmaf(e4.x, w, acc[12]); acc[13] = fmaf(e4.y, w, acc[13]);
        acc[14] = fmaf(e4.z, w, acc[14]); acc[15] = fmaf(e4.w, w, acc[15]);
    }

#pragma unroll
    for (int r = 0; r < 16; r++) {
        int idx = (m0 + r) * UU + u;
        if (KMODE) {
            g_k [idx] = acc[r];
            g_kc[idx] = acc[r] * C2LOG2E;
        } else {
            g_qc[idx] = acc[r] * C2LOG2E;
        }
    }
}

// ---------------------------------------------------------------------------
// Attention: one CTA per 8 q-rows of one batch. 256 threads (8 warps).
//   Phase 1: scores -> global (weights region of d_out)
//   Phase 2: in-place softmax (warp per q-row)
//   Phase 3: context = weights @ k, k staged in smem chunks
// ---------------------------------------------------------------------------
__global__ void __launch_bounds__(256) attn_kernel(const float* __restrict__ scale,
                                                   float* __restrict__ out) {
    __shared__ __align__(16) float s_qc[QB][UU];   // 4 KB
    __shared__ __align__(16) float s_s2[UU];       // -2*scale
    __shared__ float s_sumscale;
    __shared__ __align__(16) float s_kch[64][UU];  // 32 KB k chunk for phase 3
    __shared__ __align__(16) float s_w[QB][64];    // 2 KB weight chunk for phase 3

    const int tid   = threadIdx.x;
    const int lane  = tid & 31;
    const int wp    = tid >> 5;
    const int b     = blockIdx.x >> 5;          // 32 CTAs per batch
    const int q0    = (blockIdx.x & 31) * QB;
    const int qrow0 = b * TQ + q0;              // global q-row base

    float* ctx  = out;                          // [B*TQ, U]
    float* wout = out + BB * TQ * UU;           // [B*TQ, TV]

    // --- setup ---
    for (int i = tid; i < QB * UU; i += 256)
        s_qc[i >> 7][i & 127] = g_qc[(qrow0 + (i >> 7)) * UU + (i & 127)];
    if (tid < UU) s_s2[tid] = -2.f * scale[tid];
    if (tid < 32) {
        float s = 0.f;
#pragma unroll
        for (int j = 0; j < 4; j++) s += scale[tid + 32 * j];
#pragma unroll
        for (int o = 16; o > 0; o >>= 1) s += __shfl_xor_sync(0xffffffffu, s, o);
        if (tid == 0) s_sumscale = s;
    }
    __syncthreads();

    // --- Phase 1: scores.  Warp wp handles v in [wp*256, wp*256+256).
    //     Lane covers u = 4*lane..4*lane+3 (coalesced 512B kc row per v).
    //     u-components x,y use MUFU rcp; z,w use the FMA-pipe Newton rcp. ---
    float qc[QB][4];
    {
        const float4* q4 = reinterpret_cast<const float4*>(&s_qc[0][0]);
#pragma unroll
        for (int q = 0; q < QB; q++) {
            float4 t = q4[q * 32 + lane];
            qc[q][0] = t.x; qc[q][1] = t.y; qc[q][2] = t.z; qc[q][3] = t.w;
        }
    }
    const float4 s2v = reinterpret_cast<const float4*>(s_s2)[lane];
    const float  sumscale = s_sumscale;
    const float4* kc4 = reinterpret_cast<const float4*>(g_kc) + (size_t)b * TV * (UU / 4);

    for (int i = 0; i < TV / 8; i++) {
        const int v = wp * (TV / 8) + i;
        const float4 kc = kc4[v * 32 + lane];
        float p[QB];
#pragma unroll
        for (int q = 0; q < QB; q++) {
            float x, e, r, a;
            x = qc[q][0] + kc.x; e = fex2(x); r = frcp(e + 1.f);      a = s2v.x * r;
            x = qc[q][1] + kc.y; e = fex2(x); r = frcp(e + 1.f);      a = fmaf(s2v.y, r, a);
            x = qc[q][2] + kc.z; e = fex2(x); r = frcp_fast(e + 1.f); a = fmaf(s2v.z, r, a);
            x = qc[q][3] + kc.w; e = fex2(x); r = frcp_fast(e + 1.f); a = fmaf(s2v.w, r, a);
            p[q] = a;
        }
#pragma unroll
        for (int q = 0; q < QB; q++) {
#pragma unroll
            for (int o = 16; o > 0; o >>= 1)
                p[q] += __shfl_xor_sync(0xffffffffu, p[q], o);
        }
        if (lane == 0) {
#pragma unroll
            for (int q = 0; q < QB; q++)
                wout[(size_t)(qrow0 + q) * TV + v] = sumscale + p[q];
        }
    }
    __syncthreads();   // block-wide visibility of score writes

    // --- Phase 2: softmax in-place over wout rows. Warp wp -> row q=wp. ---
    {
        float* row = wout + (size_t)(qrow0 + wp) * TV;
        float m = -1e30f;
        for (int j = lane; j < TV; j += 32) m = fmaxf(m, row[j]);
#pragma unroll
        for (int o = 16; o > 0; o >>= 1)
            m = fmaxf(m, __shfl_xor_sync(0xffffffffu, m, o));
        const float mc = m * LOG2E;
        float s = 0.f;
        for (int j = lane; j < TV; j += 32) {
            float e = fex2(fmaf(row[j], LOG2E, -mc));
            row[j] = e;
            s += e;
        }
#pragma unroll
        for (int o = 16; o > 0; o >>= 1) s += __shfl_xor_sync(0xffffffffu, s, o);
        const float rinv = frcp(s);
        for (int j = lane; j < TV; j += 32) row[j] *= rinv;
    }
    __syncthreads();

    // --- Phase 3: context[q, u] = sum_v w[q,v] * k[v,u].
    //     Warp wp -> q=wp, lane -> u4.  k staged in 64-row smem chunks. ---
    {
        const float4* k4 = reinterpret_cast<const float4*>(g_k) + (size_t)b * TV * (UU / 4);
        float4 acc = make_float4(0.f, 0.f, 0.f, 0.f);
        for (int c = 0; c < TV / 64; c++) {
            for (int i = tid; i < 64 * (UU / 4); i += 256) {
                int vl = i >> 5, u4 = i & 31;
                reinterpret_cast<float4*>(&s_kch[vl][0])[u4] = k4[(c * 64 + vl) * 32 + u4];
            }
            for (int i = tid; i < QB * 64; i += 256) {
                int r = i >> 6, vl = i & 63;
                s_w[r][vl] = wout[(size_t)(qrow0 + r) * TV + c * 64 + vl];
            }
            __syncthreads();
#pragma unroll 8
            for (int vl = 0; vl < 64; vl++) {
                float  wv = s_w[wp][vl];
                float4 kv = reinterpret_cast<const float4*>(&s_kch[vl][0])[lane];
                acc.x = fmaf(wv, kv.x, acc.x);
                acc.y = fmaf(wv, kv.y, acc.y);
                acc.z = fmaf(wv, kv.z, acc.z);
                acc.w = fmaf(wv, kv.w, acc.w);
            }
            __syncthreads();
        }
        reinterpret_cast<float4*>(ctx)[(size_t)(qrow0 + wp) * 32 + lane] = acc;
    }
}

// ---------------------------------------------------------------------------
extern "C" void kernel_launch(void* const* d_in, const int* in_sizes, int n_in,
                              void* d_out, int out_size) {
    const float* dec_query  = (const float*)d_in[0];  // [4,256,512]
    const float* enc_values = (const float*)d_in[1];  // [4,2048,512]
    const float* W1         = (const float*)d_in[2];  // [512,128]
    const float* W2         = (const float*)d_in[3];  // [512,128]
    const float* scale      = (const float*)d_in[4];  // [128]
    float* out = (float*)d_out;   // context [4*256*128] then weights [4*256*2048]

    proj_kernel<false><<<(BB * TQ) / 16, 128>>>(dec_query, W1);
    proj_kernel<true ><<<(BB * TV) / 16, 128>>>(enc_values, W2);
    attn_kernel<<<(BB * TQ) / QB, 256>>>(scale, out);
}

// round 12
// speedup vs baseline: 1.4076x; 1.4076x over previous
#include <cuda_runtime.h>

// ---------------------------------------------------------------------------
// BahdanauAttention (Keras AdditiveAttention) on GB300, round 12 (= R6..R11,
// held unchanged through broker outage; triple-audited best candidate).
//   q = dec_query @ W1;  k = enc_values @ W2
//   scores[b,q,v] = sum_u scale[u]*tanh(q+k);  weights = softmax_v;
//   context = weights @ k;  out = concat(context, weights)
// B=4, Tq=256, Tv=2048, D=512, U=128.
//
// Separable exponential: tanh(q+k) = 1 - 2/(exp2(cq)*exp2(ck) + 1).
// exp2 factors precomputed in the projection epilogue (g_eq, g_ekT), so the
// 268M-element score loop is:  y = fma(eq, ek, 1);  r = 1/y;  acc += s2*r.
// Reciprocal split 6 MUFU : 2 Newton balances MUFU (96cyc) vs FMA (96cyc)
// per u-iter/SMSP (ex2-based loop was 176; mul+add variant 112).
//
// Structure:
//  * merged one-wave projection GEMM (144 CTAs, 64x128 tile, K-chunk 32)
//  * k exponentials stored transposed [u][v]: score phase maps lane->v,
//    zero shuffles, accumulators are scores directly, coalesced stores
//  * in-place softmax, then smem-staged context GEMM
// ---------------------------------------------------------------------------

#define BB 4
#define TQ 256
#define TV 2048
#define DK 512
#define UU 128
#define QB 8

#define C2LOG2E 2.8853900817779268f   // 2*log2(e)
#define LOG2E   1.4426950408889634f

__device__ float g_eq [BB * TQ * UU];   // exp2(2log2e * q), row-major [row][u]
__device__ float g_k  [BB * TV * UU];   // enc_values @ W2 (raw), row-major
__device__ float g_ekT[BB * UU * TV];   // exp2(2log2e * k), TRANSPOSED [b][u][v]

__device__ __forceinline__ float fex2(float x) {
    float y; asm("ex2.approx.ftz.f32 %0, %1;" : "=f"(y) : "f"(x)); return y;
}
__device__ __forceinline__ float frcp(float x) {
    float y; asm("rcp.approx.ftz.f32 %0, %1;" : "=f"(y) : "f"(x)); return y;
}
// FMA/ALU-pipe reciprocal: magic seed + 2 Newton steps, rel err ~6e-6.
// Valid for y in [1, ~1e30); here y = eq*ek + 1 >= 1.
__device__ __forceinline__ float frcp_fast(float y) {
    float r = __int_as_float(0x7EF311C3 - __float_as_int(y));
    r = r * fmaf(-y, r, 2.0f);
    r = r * fmaf(-y, r, 2.0f);
    return r;
}

// ---------------------------------------------------------------------------
// Merged projection GEMM. CTA tile: 64 rows x 128 cols, K=512 in chunks of 32.
// CTAs 0..15  -> q projection -> g_eq = exp2(scaled q).
// CTAs 16..143 -> k projection -> g_k raw + g_ekT = exp2(scaled k) transposed.
// 256 threads; tm=tid/32 -> rows tm*8..+7, tn=tid%32 -> cols tn*4..+3.
// ---------------------------------------------------------------------------
__global__ void __launch_bounds__(256) proj_kernel(const float* __restrict__ dq,
                                                   const float* __restrict__ ev,
                                                   const float* __restrict__ W1,
                                                   const float* __restrict__ W2) {
    __shared__ __align__(16) float Xs[64 * 33];    // [row][k], stride 33: conflict-free
    __shared__ __align__(16) float Ws[32 * 132];   // [k][u],  stride 132: 16B-aligned

    const int  tid = threadIdx.x;
    const bool isQ = blockIdx.x < 16;
    const float* X = isQ ? dq : ev;
    const float* W = isQ ? W1 : W2;
    const int  m0  = (isQ ? (int)blockIdx.x : (int)blockIdx.x - 16) * 64;
    const int  tn  = tid & 31;
    const int  tm  = tid >> 5;

    float acc[8][4];
#pragma unroll
    for (int r = 0; r < 8; r++)
#pragma unroll
        for (int j = 0; j < 4; j++) acc[r][j] = 0.f;

    const float4* X4 = reinterpret_cast<const float4*>(X);
    const float4* W4 = reinterpret_cast<const float4*>(W);

    for (int kc = 0; kc < DK; kc += 32) {
#pragma unroll
        for (int t = 0; t < 2; t++) {              // X chunk: 64x32
            int idx = tid + t * 256;
            int row = idx >> 3, col = idx & 7;
            float4 v = X4[(size_t)(m0 + row) * (DK / 4) + (kc >> 2) + col];
            Xs[row * 33 + col * 4 + 0] = v.x;
            Xs[row * 33 + col * 4 + 1] = v.y;
            Xs[row * 33 + col * 4 + 2] = v.z;
            Xs[row * 33 + col * 4 + 3] = v.w;
        }
#pragma unroll
        for (int t = 0; t < 4; t++) {              // W chunk: 32x128
            int idx = tid + t * 256;
            int row = idx >> 5, col = idx & 31;
            float4 v = W4[(size_t)(kc + row) * (UU / 4) + col];
            *reinterpret_cast<float4*>(&Ws[row * 132 + col * 4]) = v;
        }
        __syncthreads();

#pragma unroll
        for (int k = 0; k < 32; k++) {
            float4 wv = *reinterpret_cast<const float4*>(&Ws[k * 132 + tn * 4]);
#pragma unroll
            for (int r = 0; r < 8; r++) {
                float xv = Xs[(tm * 8 + r) * 33 + k];   // warp-broadcast
                acc[r][0] = fmaf(xv, wv.x, acc[r][0]);
                acc[r][1] = fmaf(xv, wv.y, acc[r][1]);
                acc[r][2] = fmaf(xv, wv.z, acc[r][2]);
                acc[r][3] = fmaf(xv, wv.w, acc[r][3]);
            }
        }
        __syncthreads();
    }

    if (isQ) {
#pragma unroll
        for (int r = 0; r < 8; r++) {
            float4 o = make_float4(fex2(acc[r][0] * C2LOG2E), fex2(acc[r][1] * C2LOG2E),
                                   fex2(acc[r][2] * C2LOG2E), fex2(acc[r][3] * C2LOG2E));
            reinterpret_cast<float4*>(g_eq)[(size_t)(m0 + tm * 8 + r) * (UU / 4) + tn] = o;
        }
    } else {
        const int b     = m0 / TV;           // 64-row tile never straddles a batch
        const int vloc0 = (m0 % TV) + tm * 8;
#pragma unroll
        for (int r = 0; r < 8; r++) {
            float4 o = make_float4(acc[r][0], acc[r][1], acc[r][2], acc[r][3]);
            reinterpret_cast<float4*>(g_k)[(size_t)(m0 + tm * 8 + r) * (UU / 4) + tn] = o;
            const int v = vloc0 + r;
#pragma unroll
            for (int j = 0; j < 4; j++)      // transposed scatter (tiny traffic)
                g_ekT[((size_t)b * UU + tn * 4 + j) * TV + v] = fex2(acc[r][j] * C2LOG2E);
        }
    }
}

// ---------------------------------------------------------------------------
// Attention: one CTA per 8 q-rows of one batch. 256 threads / 8 warps.
//   Phase 1: scores (lane = v, loop u, no shuffles) -> weights region of out
//   Phase 2: in-place softmax (warp per q-row)
//   Phase 3: context = weights @ k (smem-staged k chunks)
// ---------------------------------------------------------------------------
__global__ void __launch_bounds__(256) attn_kernel(const float* __restrict__ scale,
                                                   float* __restrict__ out) {
    __shared__ __align__(16) float s_eqT[UU * 12];   // [u][q], stride 12 floats (48B)
    __shared__ __align__(16) float s_s2[UU];         // -2*scale
    __shared__ float s_sumscale;
    __shared__ __align__(16) float s_kch[64 * UU];   // 32 KB k chunk (phase 3)
    __shared__ __align__(16) float s_w[QB * 64];     // 2 KB weights chunk (phase 3)

    const int tid   = threadIdx.x;
    const int lane  = tid & 31;
    const int wp    = tid >> 5;
    const int b     = blockIdx.x >> 5;
    const int q0    = (blockIdx.x & 31) * QB;
    const int qrow0 = b * TQ + q0;

    float* ctx  = out;
    float* wout = out + BB * TQ * UU;

    // --- setup: stage eq transposed, scales ---
    for (int i = tid; i < QB * UU; i += 256) {
        int q = i >> 7, u = i & 127;
        s_eqT[u * 12 + q] = g_eq[(size_t)(qrow0 + q) * UU + u];
    }
    if (tid < UU) s_s2[tid] = -2.f * scale[tid];
    if (tid < 32) {
        float s = 0.f;
#pragma unroll
        for (int j = 0; j < 4; j++) s += scale[tid + 32 * j];
#pragma unroll
        for (int o = 16; o > 0; o >>= 1) s += __shfl_xor_sync(0xffffffffu, s, o);
        if (tid == 0) s_sumscale = s;
    }
    __syncthreads();
    const float sumscale = s_sumscale;

    // --- Phase 1: scores. Warp wp owns v in [wp*256, wp*256+256), lane = v
    //     within each 32-wide group. Accumulators ARE scores[q][v].
    //     Inner body: y = fma(eq, ek, 1); r = rcp(y); acc += s2*r. ---
    {
        const float* ekT = g_ekT + (size_t)b * UU * TV;
        for (int c = 0; c < 8; c++) {
            const int vb = wp * 256 + c * 32 + lane;
            float acc[QB];
#pragma unroll
            for (int q = 0; q < QB; q++) acc[q] = 0.f;

#pragma unroll 4
            for (int u = 0; u < UU; u++) {
                const float ek  = ekT[(size_t)u * TV + vb];   // coalesced LDG
                const float s2u = s_s2[u];                    // broadcast LDS
                const float4 qA = *reinterpret_cast<const float4*>(&s_eqT[u * 12]);
                const float4 qB = *reinterpret_cast<const float4*>(&s_eqT[u * 12 + 4]);
                float qq[QB] = { qA.x, qA.y, qA.z, qA.w, qB.x, qB.y, qB.z, qB.w };
#pragma unroll
                for (int q = 0; q < QB; q++) {
                    float y = fmaf(qq[q], ek, 1.0f);
                    float r = (q < 6) ? frcp(y) : frcp_fast(y);  // 6:2 pipe split
                    acc[q] = fmaf(s2u, r, acc[q]);
                }
            }
#pragma unroll
            for (int q = 0; q < QB; q++)
                wout[(size_t)(qrow0 + q) * TV + vb] = sumscale + acc[q];
        }
    }
    __syncthreads();

    // --- Phase 2: softmax in-place. Warp wp -> row q=wp. ---
    {
        float* row = wout + (size_t)(qrow0 + wp) * TV;
        float m = -1e30f;
        for (int j = lane; j < TV; j += 32) m = fmaxf(m, row[j]);
#pragma unroll
        for (int o = 16; o > 0; o >>= 1)
            m = fmaxf(m, __shfl_xor_sync(0xffffffffu, m, o));
        const float mc = m * LOG2E;
        float s = 0.f;
        for (int j = lane; j < TV; j += 32) {
            float e = fex2(fmaf(row[j], LOG2E, -mc));
            row[j] = e;
            s += e;
        }
#pragma unroll
        for (int o = 16; o > 0; o >>= 1) s += __shfl_xor_sync(0xffffffffu, s, o);
        const float rinv = frcp(s);
        for (int j = lane; j < TV; j += 32) row[j] *= rinv;
    }
    __syncthreads();

    // --- Phase 3: context[q,u] = sum_v w[q,v] * k[v,u]. Warp wp -> q=wp. ---
    {
        const float4* k4 = reinterpret_cast<const float4*>(g_k) + (size_t)b * TV * (UU / 4);
        float4 acc = make_float4(0.f, 0.f, 0.f, 0.f);
        for (int c = 0; c < TV / 64; c++) {
            for (int i = tid; i < 64 * (UU / 4); i += 256) {
                int vl = i >> 5, u4 = i & 31;
                reinterpret_cast<float4*>(&s_kch[vl * UU])[u4] = k4[(size_t)(c * 64 + vl) * 32 + u4];
            }
            for (int i = tid; i < QB * 64; i += 256) {
                int r = i >> 6, vl = i & 63;
                s_w[r * 64 + vl] = wout[(size_t)(qrow0 + r) * TV + c * 64 + vl];
            }
            __syncthreads();
#pragma unroll 8
            for (int vl = 0; vl < 64; vl++) {
                float  wv = s_w[wp * 64 + vl];
                float4 kv = reinterpret_cast<const float4*>(&s_kch[vl * UU])[lane];
                acc.x = fmaf(wv, kv.x, acc.x);
                acc.y = fmaf(wv, kv.y, acc.y);
                acc.z = fmaf(wv, kv.z, acc.z);
                acc.w = fmaf(wv, kv.w, acc.w);
            }
            __syncthreads();
        }
        reinterpret_cast<float4*>(ctx)[(size_t)(qrow0 + wp) * 32 + lane] = acc;
    }
}

// ---------------------------------------------------------------------------
extern "C" void kernel_launch(void* const* d_in, const int* in_sizes, int n_in,
                              void* d_out, int out_size) {
    const float* dec_query  = (const float*)d_in[0];  // [4,256,512]
    const float* enc_values = (const float*)d_in[1];  // [4,2048,512]
    const float* W1         = (const float*)d_in[2];  // [512,128]
    const float* W2         = (const float*)d_in[3];  // [512,128]
    const float* scale      = (const float*)d_in[4];  // [128]
    float* out = (float*)d_out;   // context [4*256*128] then weights [4*256*2048]

    proj_kernel<<<144, 256>>>(dec_query, enc_values, W1, W2);
    attn_kernel<<<(BB * TQ) / QB, 256>>>(scale, out);
}